// round 5
// baseline (speedup 1.0000x reference)
#include <cuda_runtime.h>
#include <cuda_bf16.h>
#include <math.h>

#define F 128
#define NMAX 50000
#define EMAX 800000
#define CAP 64      // bucket capacity per destination row (P(deg>=64) ~ 0)
#define MT 64       // rows per epilogue tile

// static scratch (no allocations allowed; zero-initialized at module load)
__device__ float  g_S[(size_t)NMAX * F];           // S = (1-a)*A@x + a*h0
__device__ float2 g_slots[(size_t)NMAX * CAP];     // (src_bits, w) buckets
__device__ int    g_cnt[NMAX];                     // self-cleaning (gather resets)
__device__ float4 g_over[EMAX];                    // overflow edges (src,dst,w,-)
__device__ int    g_overcnt;                       // reset by epilogue

// ---------------------------------------------------------------------------
// Kernel 1: bucket fill. One thread per edge. Overflow -> side list.
// g_cnt enters zeroed (static init on first call, gather-reset on later calls).
// ---------------------------------------------------------------------------
__global__ void fill_kernel(const float* __restrict__ edge_w,
                            const int* __restrict__ edge_src,
                            const int* __restrict__ edge_dst,
                            int E) {
    int e = blockIdx.x * blockDim.x + threadIdx.x;
    if (e >= E) return;
    int d = edge_dst[e];
    int s = edge_src[e];
    float w = edge_w[e];
    int pos = atomicAdd(&g_cnt[d], 1);
    if (pos < CAP) {
        g_slots[(size_t)d * CAP + pos] = make_float2(__int_as_float(s), w);
    } else {
        int o = atomicAdd(&g_overcnt, 1);
        if (o < EMAX)
            g_over[o] = make_float4(__int_as_float(s), __int_as_float(d), w, 0.f);
    }
}

// ---------------------------------------------------------------------------
// Kernel 2: gather + S fuse + counter self-reset. One warp per row.
//   S[row] = (1-alpha) * (sum_e w_e * x[src_e])  + alpha * h0[row]
// Lane owns a float4 chunk; edges broadcast via shfl. Overflow edges (never
// in practice) are drained here by the owning row's warp.
// ---------------------------------------------------------------------------
__global__ void __launch_bounds__(256)
gather_kernel(const float* __restrict__ x,
              const float* __restrict__ h0,
              const float* __restrict__ alpha_p,
              int Nn) {
    int gtid = blockIdx.x * blockDim.x + threadIdx.x;
    int row = gtid >> 5;
    int lane = gtid & 31;
    if (row >= Nn) return;

    float alpha = alpha_p[0];
    float oma = 1.0f - alpha;

    // issue h0 load early (independent of edge loop)
    float4 hv = ((const float4*)(h0 + (size_t)row * F))[lane];

    int cnt_raw = g_cnt[row];
    if (lane == 0) g_cnt[row] = 0;         // self-reset for next invocation
    int cnt = min(cnt_raw, CAP);

    float4 acc = make_float4(0.f, 0.f, 0.f, 0.f);
    const float2* slotp = g_slots + (size_t)row * CAP;

    for (int base = 0; base < cnt; base += 32) {
        int m = min(32, cnt - base);
        float2 myslot = (lane < m) ? slotp[base + lane] : make_float2(0.f, 0.f);
        int ms = __float_as_int(myslot.x);
        #pragma unroll 4
        for (int e = 0; e < m; e++) {
            int   s  = __shfl_sync(0xffffffffu, ms, e);
            float wt = __shfl_sync(0xffffffffu, myslot.y, e);
            float4 v = ((const float4*)(x + (size_t)s * F))[lane];
            acc.x += wt * v.x;
            acc.y += wt * v.y;
            acc.z += wt * v.z;
            acc.w += wt * v.w;
        }
    }

    // overflow drain (normally dead; correct for any degree distribution)
    if (cnt_raw > CAP) {
        int oc = g_overcnt;
        if (oc > EMAX) oc = EMAX;
        for (int o = 0; o < oc; o++) {
            float4 ov = g_over[o];                 // broadcast load
            if (__float_as_int(ov.y) == row) {
                int s = __float_as_int(ov.x);
                float wt = ov.z;
                float4 v = ((const float4*)(x + (size_t)s * F))[lane];
                acc.x += wt * v.x;
                acc.y += wt * v.y;
                acc.z += wt * v.z;
                acc.w += wt * v.w;
            }
        }
    }

    float4 S;
    S.x = oma * acc.x + alpha * hv.x;
    S.y = oma * acc.y + alpha * hv.y;
    S.z = oma * acc.z + alpha * hv.z;
    S.w = oma * acc.w + alpha * hv.w;
    ((float4*)(g_S + (size_t)row * F))[lane] = S;
}

// ---------------------------------------------------------------------------
// Kernel 3: GEMM epilogue.  out = S @ W' + x,  W' = theta*W + (1-theta)*I
// FFMA2 column-pair packing: w-pairs come free from LDS.128 of Wp (adjacent
// columns); 16 independent accumulators per thread. Also resets g_overcnt.
// ---------------------------------------------------------------------------
#define PACK2(dst, lo, hi) \
    asm("mov.b64 %0, {%1, %2};" : "=l"(dst) : "f"(lo), "f"(hi))
#define UNPACK2(lo, hi, src) \
    asm("mov.b64 {%0, %1}, %2;" : "=f"(lo), "=f"(hi) : "l"(src))
#define FMA2(acc, a, b) \
    asm("fma.rn.f32x2 %0, %1, %2, %0;" : "+l"(acc) : "l"(a), "l"(b))

__global__ void __launch_bounds__(256, 2)
epilogue_kernel(const float* __restrict__ x,
                const float* __restrict__ weight,
                const float* __restrict__ lamda_p,
                const int* __restrict__ l_p,
                float* __restrict__ out,
                int Nn) {
    extern __shared__ float sh[];
    float* Wp = sh;            // 128x128 = 64 KB
    float* st = sh + F * F;    // 64x128  = 32 KB

    int tid = threadIdx.x;
    int cg = tid & 31;         // column group: cols 4cg .. 4cg+3
    int rg = tid >> 5;         // row group: rows 8rg .. 8rg+7

    if (blockIdx.x == 0 && tid == 0) g_overcnt = 0;   // reset for next call

    float theta = logf(lamda_p[0] / (float)l_p[0] + 1.0f);
    float omt = 1.0f - theta;

    // W'[k][j] = theta*W[k][j] + (k==j ? 1-theta : 0)
    for (int i = tid; i < F * F; i += 256) {
        int k = i >> 7;
        int j = i & 127;
        float v = theta * weight[i];
        if (k == j) v += omt;
        Wp[i] = v;
    }
    __syncthreads();

    int ntiles = (Nn + MT - 1) / MT;
    for (int t = blockIdx.x; t < ntiles; t += gridDim.x) {
        int row0 = t * MT;

        // load S tile (coalesced float4), zero-pad tail rows
        for (int i = tid; i < MT * (F / 4); i += 256) {
            int r = i >> 5;
            int q = i & 31;
            float4 v = (row0 + r < Nn)
                ? ((const float4*)(g_S + (size_t)(row0 + r) * F))[q]
                : make_float4(0.f, 0.f, 0.f, 0.f);
            *(float4*)&st[r * F + q * 4] = v;
        }
        __syncthreads();

        unsigned long long acc[8][2];
        #pragma unroll
        for (int r = 0; r < 8; r++) { acc[r][0] = 0ull; acc[r][1] = 0ull; }

        for (int k = 0; k < F; k += 2) {
            float4 w0 = *(const float4*)&Wp[k * F + 4 * cg];
            float4 w1 = *(const float4*)&Wp[(k + 1) * F + 4 * cg];
            unsigned long long wp00, wp01, wp10, wp11;
            PACK2(wp00, w0.x, w0.y); PACK2(wp01, w0.z, w0.w);
            PACK2(wp10, w1.x, w1.y); PACK2(wp11, w1.z, w1.w);
            #pragma unroll
            for (int r = 0; r < 8; r++) {
                float2 s2 = *(const float2*)&st[(rg * 8 + r) * F + k]; // bcast
                unsigned long long sp0, sp1;
                PACK2(sp0, s2.x, s2.x);
                PACK2(sp1, s2.y, s2.y);
                FMA2(acc[r][0], sp0, wp00);
                FMA2(acc[r][1], sp0, wp01);
                FMA2(acc[r][0], sp1, wp10);
                FMA2(acc[r][1], sp1, wp11);
            }
        }

        #pragma unroll
        for (int r = 0; r < 8; r++) {
            int row = row0 + rg * 8 + r;
            if (row < Nn) {
                float a0, a1, a2, a3;
                UNPACK2(a0, a1, acc[r][0]);
                UNPACK2(a2, a3, acc[r][1]);
                size_t base = (size_t)row * F + 4 * cg;
                float4 xv = *(const float4*)(x + base);
                float4 o = make_float4(a0 + xv.x, a1 + xv.y, a2 + xv.z, a3 + xv.w);
                *(float4*)(out + base) = o;
            }
        }
        __syncthreads();
    }
}

// ---------------------------------------------------------------------------
extern "C" void kernel_launch(void* const* d_in, const int* in_sizes, int n_in,
                              void* d_out, int out_size) {
    const float* x      = (const float*)d_in[0];
    const float* h0     = (const float*)d_in[1];
    const float* ew     = (const float*)d_in[2];
    const float* weight = (const float*)d_in[3];
    const float* lamda  = (const float*)d_in[4];
    const float* alpha  = (const float*)d_in[5];
    const int*   esrc   = (const int*)d_in[6];
    const int*   edst   = (const int*)d_in[7];
    const int*   lp     = (const int*)d_in[8];

    int Nn = in_sizes[0] / F;
    int E  = in_sizes[2];
    float* out = (float*)d_out;

    // 1) bucket fill (counters arrive zeroed: static init / gather self-reset)
    fill_kernel<<<(E + 255) / 256, 256>>>(ew, esrc, edst, E);

    // 2) gather + S fuse + counter reset (one warp per row)
    long long gthreads = (long long)Nn * 32;
    gather_kernel<<<(int)((gthreads + 255) / 256), 256>>>(x, h0, alpha, Nn);

    // 3) GEMM epilogue (+ overcnt reset)
    int smem_bytes = (F * F + MT * F) * (int)sizeof(float);   // 98304
    cudaFuncSetAttribute(epilogue_kernel,
                         cudaFuncAttributeMaxDynamicSharedMemorySize, smem_bytes);
    epilogue_kernel<<<296, 256, smem_bytes>>>(x, weight, lamda, lp, out, Nn);
}

// round 7
// speedup vs baseline: 1.4292x; 1.4292x over previous
#include <cuda_runtime.h>
#include <cuda_bf16.h>
#include <math.h>

#define F 128
#define NMAX 50000
#define EMAX 800000
#define CAP 64      // bucket capacity per destination row (P(deg>=64) ~ 1e-13)
#define MT 64       // rows per epilogue tile

// static scratch (no allocations allowed)
__device__ float  g_S[(size_t)NMAX * F];           // S = (1-a)*A@x + a*h0
__device__ float2 g_slots[(size_t)NMAX * CAP];     // (src_bits, w) buckets
__device__ int    g_cnt[NMAX];
__device__ float4 g_over[EMAX];                    // overflow edges (src,dst,w,-)
__device__ int    g_overcnt;

// ---------------------------------------------------------------------------
// Kernel 1: zero bucket counters + overflow counter
// ---------------------------------------------------------------------------
__global__ void zero_cnt_kernel(int Nn) {
    int i = blockIdx.x * blockDim.x + threadIdx.x;
    if (i < Nn) g_cnt[i] = 0;
    if (i == 0) g_overcnt = 0;
}

// ---------------------------------------------------------------------------
// Kernel 2: bucket fill. TWO edges per thread (independent atomic->store
// chains double the MLP; fill is latency-bound on the atomic round-trip).
// Thread t owns edges {t, t+half} EXCLUSIVELY (t < half guard — the R6 bug
// was threads >= half double-processing 128 edges).
// ---------------------------------------------------------------------------
__global__ void fill_kernel(const float* __restrict__ edge_w,
                            const int* __restrict__ edge_src,
                            const int* __restrict__ edge_dst,
                            int E, int half) {
    int t = blockIdx.x * blockDim.x + threadIdx.x;
    if (t >= half) return;
    #pragma unroll
    for (int u = 0; u < 2; u++) {
        int e = t + u * half;
        if (e >= E) continue;
        int d = edge_dst[e];
        int s = edge_src[e];
        float w = edge_w[e];
        int pos = atomicAdd(&g_cnt[d], 1);
        if (pos < CAP) {
            g_slots[(size_t)d * CAP + pos] = make_float2(__int_as_float(s), w);
        } else {
            int o = atomicAdd(&g_overcnt, 1);
            if (o < EMAX)
                g_over[o] = make_float4(__int_as_float(s), __int_as_float(d), w, 0.f);
        }
    }
}

// ---------------------------------------------------------------------------
// Kernel 3: gather + S fuse. One warp per row; lane owns a float4 chunk.
//   S[row] = (1-alpha) * (sum_e w_e * x[src_e]) + alpha * h0[row]
// Hot path identical to the R3 kernel; overflow edges (never in practice)
// are drained here by the owning row's warp (cold branch).
// ---------------------------------------------------------------------------
__global__ void gather_kernel(const float* __restrict__ x,
                              const float* __restrict__ h0,
                              const float* __restrict__ alpha_p,
                              int Nn) {
    int gtid = blockIdx.x * blockDim.x + threadIdx.x;
    int row = gtid >> 5;
    int lane = gtid & 31;
    if (row >= Nn) return;

    float alpha = alpha_p[0];
    float oma = 1.0f - alpha;

    int cnt_raw = g_cnt[row];
    int cnt = min(cnt_raw, CAP);

    float4 acc = make_float4(0.f, 0.f, 0.f, 0.f);
    const float2* slotp = g_slots + (size_t)row * CAP;

    for (int base = 0; base < cnt; base += 32) {
        int m = min(32, cnt - base);
        float2 myslot = (lane < m) ? slotp[base + lane] : make_float2(0.f, 0.f);
        int ms = __float_as_int(myslot.x);
        #pragma unroll 4
        for (int e = 0; e < m; e++) {
            int   s  = __shfl_sync(0xffffffffu, ms, e);
            float wt = __shfl_sync(0xffffffffu, myslot.y, e);
            float4 v = ((const float4*)(x + (size_t)s * F))[lane];
            acc.x += wt * v.x;
            acc.y += wt * v.y;
            acc.z += wt * v.z;
            acc.w += wt * v.w;
        }
    }

    // overflow drain (statistically never; correct for any degree dist)
    if (cnt_raw > CAP) {
        int oc = g_overcnt;
        if (oc > EMAX) oc = EMAX;
        for (int o = 0; o < oc; o++) {
            float4 ov = g_over[o];                 // broadcast load
            if (__float_as_int(ov.y) == row) {
                int s = __float_as_int(ov.x);
                float wt = ov.z;
                float4 v = ((const float4*)(x + (size_t)s * F))[lane];
                acc.x += wt * v.x;
                acc.y += wt * v.y;
                acc.z += wt * v.z;
                acc.w += wt * v.w;
            }
        }
    }

    float4 hv = ((const float4*)(h0 + (size_t)row * F))[lane];
    float4 S;
    S.x = oma * acc.x + alpha * hv.x;
    S.y = oma * acc.y + alpha * hv.y;
    S.z = oma * acc.z + alpha * hv.z;
    S.w = oma * acc.w + alpha * hv.w;
    ((float4*)(g_S + (size_t)row * F))[lane] = S;
}

// ---------------------------------------------------------------------------
// Kernel 4: GEMM epilogue.  out = S @ W' + x,  W' = theta*W + (1-theta)*I
// FFMA2 column-pair packing: w-pairs come free from LDS.128 of Wp (adjacent
// columns); 16 independent accumulators per thread. (Identical to R3.)
// ---------------------------------------------------------------------------
#define PACK2(dst, lo, hi) \
    asm("mov.b64 %0, {%1, %2};" : "=l"(dst) : "f"(lo), "f"(hi))
#define UNPACK2(lo, hi, src) \
    asm("mov.b64 {%0, %1}, %2;" : "=f"(lo), "=f"(hi) : "l"(src))
#define FMA2(acc, a, b) \
    asm("fma.rn.f32x2 %0, %1, %2, %0;" : "+l"(acc) : "l"(a), "l"(b))

__global__ void __launch_bounds__(256, 2)
epilogue_kernel(const float* __restrict__ x,
                const float* __restrict__ weight,
                const float* __restrict__ lamda_p,
                const int* __restrict__ l_p,
                float* __restrict__ out,
                int Nn) {
    extern __shared__ float sh[];
    float* Wp = sh;            // 128x128 = 64 KB
    float* st = sh + F * F;    // 64x128  = 32 KB

    int tid = threadIdx.x;
    int cg = tid & 31;         // column group: cols 4cg .. 4cg+3
    int rg = tid >> 5;         // row group: rows 8rg .. 8rg+7

    float theta = logf(lamda_p[0] / (float)l_p[0] + 1.0f);
    float omt = 1.0f - theta;

    // W'[k][j] = theta*W[k][j] + (k==j ? 1-theta : 0)
    for (int i = tid; i < F * F; i += 256) {
        int k = i >> 7;
        int j = i & 127;
        float v = theta * weight[i];
        if (k == j) v += omt;
        Wp[i] = v;
    }
    __syncthreads();

    int ntiles = (Nn + MT - 1) / MT;
    for (int t = blockIdx.x; t < ntiles; t += gridDim.x) {
        int row0 = t * MT;

        // load S tile (coalesced float4), zero-pad tail rows
        for (int i = tid; i < MT * (F / 4); i += 256) {
            int r = i >> 5;
            int q = i & 31;
            float4 v = (row0 + r < Nn)
                ? ((const float4*)(g_S + (size_t)(row0 + r) * F))[q]
                : make_float4(0.f, 0.f, 0.f, 0.f);
            *(float4*)&st[r * F + q * 4] = v;
        }
        __syncthreads();

        unsigned long long acc[8][2];
        #pragma unroll
        for (int r = 0; r < 8; r++) { acc[r][0] = 0ull; acc[r][1] = 0ull; }

        for (int k = 0; k < F; k += 2) {
            float4 w0 = *(const float4*)&Wp[k * F + 4 * cg];
            float4 w1 = *(const float4*)&Wp[(k + 1) * F + 4 * cg];
            unsigned long long wp00, wp01, wp10, wp11;
            PACK2(wp00, w0.x, w0.y); PACK2(wp01, w0.z, w0.w);
            PACK2(wp10, w1.x, w1.y); PACK2(wp11, w1.z, w1.w);
            #pragma unroll
            for (int r = 0; r < 8; r++) {
                float2 s2 = *(const float2*)&st[(rg * 8 + r) * F + k]; // bcast
                unsigned long long sp0, sp1;
                PACK2(sp0, s2.x, s2.x);
                PACK2(sp1, s2.y, s2.y);
                FMA2(acc[r][0], sp0, wp00);
                FMA2(acc[r][1], sp0, wp01);
                FMA2(acc[r][0], sp1, wp10);
                FMA2(acc[r][1], sp1, wp11);
            }
        }

        #pragma unroll
        for (int r = 0; r < 8; r++) {
            int row = row0 + rg * 8 + r;
            if (row < Nn) {
                float a0, a1, a2, a3;
                UNPACK2(a0, a1, acc[r][0]);
                UNPACK2(a2, a3, acc[r][1]);
                size_t base = (size_t)row * F + 4 * cg;
                float4 xv = *(const float4*)(x + base);
                float4 o = make_float4(a0 + xv.x, a1 + xv.y, a2 + xv.z, a3 + xv.w);
                *(float4*)(out + base) = o;
            }
        }
        __syncthreads();
    }
}

// ---------------------------------------------------------------------------
extern "C" void kernel_launch(void* const* d_in, const int* in_sizes, int n_in,
                              void* d_out, int out_size) {
    const float* x      = (const float*)d_in[0];
    const float* h0     = (const float*)d_in[1];
    const float* ew     = (const float*)d_in[2];
    const float* weight = (const float*)d_in[3];
    const float* lamda  = (const float*)d_in[4];
    const float* alpha  = (const float*)d_in[5];
    const int*   esrc   = (const int*)d_in[6];
    const int*   edst   = (const int*)d_in[7];
    const int*   lp     = (const int*)d_in[8];

    int Nn = in_sizes[0] / F;
    int E  = in_sizes[2];
    float* out = (float*)d_out;

    // 1) zero counters
    zero_cnt_kernel<<<(Nn + 255) / 256, 256>>>(Nn);

    // 2) bucket fill, 2 edges per thread (exclusive ownership: t < half)
    int half = (E + 1) / 2;
    fill_kernel<<<(half + 255) / 256, 256>>>(ew, esrc, edst, E, half);

    // 3) gather + S fuse (one warp per row; inline overflow drain)
    long long gthreads = (long long)Nn * 32;
    gather_kernel<<<(int)((gthreads + 255) / 256), 256>>>(x, h0, alpha, Nn);

    // 4) GEMM epilogue
    int smem_bytes = (F * F + MT * F) * (int)sizeof(float);   // 98304
    cudaFuncSetAttribute(epilogue_kernel,
                         cudaFuncAttributeMaxDynamicSharedMemorySize, smem_bytes);
    epilogue_kernel<<<296, 256, smem_bytes>>>(x, weight, lamda, lp, out, Nn);
}